// round 1
// baseline (speedup 1.0000x reference)
#include <cuda_runtime.h>

#define Bq 2
#define Sq 2048
#define Dq 1024
#define Hq 16
#define HDq 64
#define Mq (Bq*Sq)
#define SD 65   // padded smem row stride (floats) for 64-wide tiles

// Scratch (allocation-free): Q, K, V projections + attention context
__device__ float g_Q[Mq*Dq];
__device__ float g_K[Mq*Dq];
__device__ float g_V[Mq*Dq];
__device__ float g_C[Mq*Dq];

// ---------------------------------------------------------------------------
// O[m,n] = sum_k X[m,k] * W[n,k] + bias[n]
// 128x128 tile, BK=8, 256 threads, 8x8 micro-tile (strided tx+16j / ty+16i)
// ---------------------------------------------------------------------------
__global__ void __launch_bounds__(256) gemm_xwt_kernel(
    const float* __restrict__ X, const float* __restrict__ W,
    const float* __restrict__ bias, float* __restrict__ O,
    int Mdim, int Ndim, int Kdim)
{
    __shared__ float Xs[8][128];
    __shared__ float Ws[8][128];

    const int tid = threadIdx.x;
    const int tx = tid & 15, ty = tid >> 4;
    const int row0 = blockIdx.y * 128;
    const int col0 = blockIdx.x * 128;
    const int lr = tid >> 1;
    const int lh = (tid & 1) * 4;

    float acc[8][8];
#pragma unroll
    for (int i = 0; i < 8; i++)
#pragma unroll
        for (int j = 0; j < 8; j++) acc[i][j] = 0.f;

    const float* Xp = X + (size_t)(row0 + lr) * Kdim + lh;
    const float* Wp = W + (size_t)(col0 + lr) * Kdim + lh;

    for (int k0 = 0; k0 < Kdim; k0 += 8) {
        float4 xv = *(const float4*)(Xp + k0);
        float4 wv = *(const float4*)(Wp + k0);
        __syncthreads();
        Xs[lh + 0][lr] = xv.x; Xs[lh + 1][lr] = xv.y;
        Xs[lh + 2][lr] = xv.z; Xs[lh + 3][lr] = xv.w;
        Ws[lh + 0][lr] = wv.x; Ws[lh + 1][lr] = wv.y;
        Ws[lh + 2][lr] = wv.z; Ws[lh + 3][lr] = wv.w;
        __syncthreads();
#pragma unroll
        for (int kk = 0; kk < 8; kk++) {
            float a[8], b[8];
#pragma unroll
            for (int i = 0; i < 8; i++) a[i] = Xs[kk][ty + 16 * i];
#pragma unroll
            for (int j = 0; j < 8; j++) b[j] = Ws[kk][tx + 16 * j];
#pragma unroll
            for (int i = 0; i < 8; i++)
#pragma unroll
                for (int j = 0; j < 8; j++)
                    acc[i][j] = fmaf(a[i], b[j], acc[i][j]);
        }
    }

#pragma unroll
    for (int j = 0; j < 8; j++) {
        float bv = bias[col0 + tx + 16 * j];
#pragma unroll
        for (int i = 0; i < 8; i++) {
            O[(size_t)(row0 + ty + 16 * i) * Ndim + col0 + tx + 16 * j] =
                acc[i][j] + bv;
        }
    }
}

// ---------------------------------------------------------------------------
// Flash attention (fp32): 128 q-rows per block, 64-key tiles, online softmax.
// grid = (S/128, B*H), 256 threads, micro-tile 8 q-rows x 4 k-cols.
// ---------------------------------------------------------------------------
__global__ void __launch_bounds__(256) attn_kernel(
    const float* __restrict__ Q, const float* __restrict__ K,
    const float* __restrict__ V, const float* __restrict__ mask,
    float* __restrict__ Ctx)
{
    extern __shared__ float sm[];
    float* Qs = sm;                    // 128 x SD
    float* Ks = Qs + 128 * SD;         // 64 x SD
    float* Vs = Ks + 64 * SD;          // 64 x SD
    float* Ps = Vs + 64 * SD;          // 128 x SD

    const int tid = threadIdx.x;
    const int tx = tid & 15, ty = tid >> 4;
    const int bh = blockIdx.y;
    const int b = bh >> 4, h = bh & 15;
    const int q0 = blockIdx.x * 128;

    const size_t baseQ  = ((size_t)(b * Sq + q0)) * Dq + h * HDq;
    const size_t baseKV = ((size_t)(b * Sq)) * Dq + h * HDq;

    // Load Q tile, fold in 1/sqrt(HD) = 0.125
#pragma unroll
    for (int it = 0; it < 8; it++) {
        int v = tid + it * 256;
        int r = v >> 4, c4 = (v & 15) * 4;
        float4 qv = *(const float4*)(Q + baseQ + (size_t)r * Dq + c4);
        float* dst = Qs + r * SD + c4;
        dst[0] = qv.x * 0.125f; dst[1] = qv.y * 0.125f;
        dst[2] = qv.z * 0.125f; dst[3] = qv.w * 0.125f;
    }

    float m[8], l[8], o[8][4];
#pragma unroll
    for (int i = 0; i < 8; i++) {
        m[i] = -1e30f; l[i] = 0.f;
#pragma unroll
        for (int j = 0; j < 4; j++) o[i][j] = 0.f;
    }

    for (int k0 = 0; k0 < Sq; k0 += 64) {
        __syncthreads();   // previous PV done before overwriting Ks/Vs
#pragma unroll
        for (int it = 0; it < 4; it++) {
            int v = tid + it * 256;
            int r = v >> 4, c4 = (v & 15) * 4;
            float4 kv = *(const float4*)(K + baseKV + (size_t)(k0 + r) * Dq + c4);
            float4 vv = *(const float4*)(V + baseKV + (size_t)(k0 + r) * Dq + c4);
            float* kd = Ks + r * SD + c4;
            kd[0] = kv.x; kd[1] = kv.y; kd[2] = kv.z; kd[3] = kv.w;
            float* vd = Vs + r * SD + c4;
            vd[0] = vv.x; vd[1] = vv.y; vd[2] = vv.z; vd[3] = vv.w;
        }
        float mv[4];
#pragma unroll
        for (int j = 0; j < 4; j++)
            mv[j] = mask[b * Sq + k0 + tx + 16 * j];
        __syncthreads();

        // S = Q K^T  (scores)
        float s[8][4];
#pragma unroll
        for (int i = 0; i < 8; i++)
#pragma unroll
            for (int j = 0; j < 4; j++) s[i][j] = 0.f;

#pragma unroll 8
        for (int d = 0; d < 64; d++) {
            float kb[4];
#pragma unroll
            for (int j = 0; j < 4; j++) kb[j] = Ks[(tx + 16 * j) * SD + d];
#pragma unroll
            for (int i = 0; i < 8; i++) {
                float qa = Qs[(ty + 16 * i) * SD + d];
#pragma unroll
                for (int j = 0; j < 4; j++)
                    s[i][j] = fmaf(qa, kb[j], s[i][j]);
            }
        }

        // mask + online softmax (row reductions across the 16 tx lanes)
#pragma unroll
        for (int i = 0; i < 8; i++) {
#pragma unroll
            for (int j = 0; j < 4; j++) s[i][j] += mv[j];
            float rm = fmaxf(fmaxf(s[i][0], s[i][1]), fmaxf(s[i][2], s[i][3]));
#pragma unroll
            for (int off = 8; off > 0; off >>= 1)
                rm = fmaxf(rm, __shfl_xor_sync(0xffffffffu, rm, off, 16));
            float mn = fmaxf(m[i], rm);
            float alpha = __expf(m[i] - mn);
            m[i] = mn;
            float rs = 0.f;
#pragma unroll
            for (int j = 0; j < 4; j++) {
                s[i][j] = __expf(s[i][j] - mn);
                rs += s[i][j];
            }
#pragma unroll
            for (int off = 8; off > 0; off >>= 1)
                rs += __shfl_xor_sync(0xffffffffu, rs, off, 16);
            l[i] = l[i] * alpha + rs;
#pragma unroll
            for (int j = 0; j < 4; j++) o[i][j] *= alpha;
        }

        // stage P through smem for the PV product
#pragma unroll
        for (int i = 0; i < 8; i++)
#pragma unroll
            for (int j = 0; j < 4; j++)
                Ps[(ty + 16 * i) * SD + tx + 16 * j] = s[i][j];
        __syncthreads();

#pragma unroll 8
        for (int c = 0; c < 64; c++) {
            float vb[4];
#pragma unroll
            for (int j = 0; j < 4; j++) vb[j] = Vs[c * SD + tx + 16 * j];
#pragma unroll
            for (int i = 0; i < 8; i++) {
                float pa = Ps[(ty + 16 * i) * SD + c];
#pragma unroll
                for (int j = 0; j < 4; j++)
                    o[i][j] = fmaf(pa, vb[j], o[i][j]);
            }
        }
    }

#pragma unroll
    for (int i = 0; i < 8; i++) {
        float inv = 1.0f / l[i];
#pragma unroll
        for (int j = 0; j < 4; j++)
            Ctx[baseQ + (size_t)(ty + 16 * i) * Dq + tx + 16 * j] = o[i][j] * inv;
    }
}

// ---------------------------------------------------------------------------

extern "C" void kernel_launch(void* const* d_in, const int* in_sizes, int n_in,
                              void* d_out, int out_size)
{
    const float* hs   = (const float*)d_in[0];
    const float* mask = (const float*)d_in[1];
    const float* Wq   = (const float*)d_in[2];
    const float* bq   = (const float*)d_in[3];
    const float* Wk   = (const float*)d_in[4];
    const float* bk   = (const float*)d_in[5];
    const float* Wv   = (const float*)d_in[6];
    const float* bv   = (const float*)d_in[7];
    const float* Wo   = (const float*)d_in[8];
    const float* bo   = (const float*)d_in[9];
    float* out = (float*)d_out;

    float *q, *k, *v, *c;
    cudaGetSymbolAddress((void**)&q, g_Q);
    cudaGetSymbolAddress((void**)&k, g_K);
    cudaGetSymbolAddress((void**)&v, g_V);
    cudaGetSymbolAddress((void**)&c, g_C);

    dim3 ggrid(Dq / 128, Mq / 128);
    gemm_xwt_kernel<<<ggrid, 256>>>(hs, Wq, bq, q, Mq, Dq, Dq);
    gemm_xwt_kernel<<<ggrid, 256>>>(hs, Wk, bk, k, Mq, Dq, Dq);
    gemm_xwt_kernel<<<ggrid, 256>>>(hs, Wv, bv, v, Mq, Dq, Dq);

    size_t smem = (size_t)(128 + 64 + 64 + 128) * SD * sizeof(float);
    cudaFuncSetAttribute(attn_kernel,
                         cudaFuncAttributeMaxDynamicSharedMemorySize, (int)smem);
    dim3 agrid(Sq / 128, Bq * Hq);
    attn_kernel<<<agrid, 256, smem>>>(q, k, v, mask, c);

    gemm_xwt_kernel<<<ggrid, 256>>>(c, Wo, bo, out, Mq, Dq, Dq);
}

// round 2
// speedup vs baseline: 2.2067x; 2.2067x over previous
#include <cuda_runtime.h>
#include <cuda_bf16.h>
#include <cstdint>

#define Bq 2
#define Sq 2048
#define Dq 1024
#define Hq 16
#define HDq 64
#define Mq (Bq*Sq)

// Scratch (allocation-free)
__device__ float g_Q[Mq*Dq];
__device__ float g_K[Mq*Dq];
__device__ float g_V[Mq*Dq];
__device__ float g_C[Mq*Dq];

// ---------------------------------------------------------------------------
// m16n8k16 bf16 mma, fp32 accum
// ---------------------------------------------------------------------------
__device__ __forceinline__ void mma16816(float* c, const uint32_t* a,
                                         uint32_t b0, uint32_t b1) {
    asm volatile("mma.sync.aligned.m16n8k16.row.col.f32.bf16.bf16.f32 "
                 "{%0,%1,%2,%3}, {%4,%5,%6,%7}, {%8,%9}, {%0,%1,%2,%3};"
                 : "+f"(c[0]), "+f"(c[1]), "+f"(c[2]), "+f"(c[3])
                 : "r"(a[0]), "r"(a[1]), "r"(a[2]), "r"(a[3]),
                   "r"(b0), "r"(b1));
}

// split (x,y) into packed bf16x2 hi and lo parts (hi+lo ~ 16 mantissa bits)
__device__ __forceinline__ void split2(float x, float y,
                                       uint32_t& hi, uint32_t& lo) {
    __nv_bfloat16 hx = __float2bfloat16_rn(x);
    __nv_bfloat16 hy = __float2bfloat16_rn(y);
    __nv_bfloat162 h2 = __halves2bfloat162(hx, hy);
    __nv_bfloat162 l2 = __halves2bfloat162(
        __float2bfloat16_rn(x - __bfloat162float(hx)),
        __float2bfloat16_rn(y - __bfloat162float(hy)));
    hi = *reinterpret_cast<uint32_t*>(&h2);
    lo = *reinterpret_cast<uint32_t*>(&l2);
}

// ---------------------------------------------------------------------------
// O[m,n] = X[m,:].W[n,:] + bias[n], M=4096 N=K=1024, bf16x3
// 128x128 tile, BK=16, 256 thr, warp tile 64x32
// smem rows: 8 bf16-pair cols, stride GS=12 (conflict-free: 12g mod 32 distinct)
// ---------------------------------------------------------------------------
#define GS 12

__global__ void __launch_bounds__(256) gemm_kernel(
    const float* __restrict__ X, const float* __restrict__ W,
    const float* __restrict__ bias, float* __restrict__ O)
{
    __shared__ uint32_t Xh[128*GS], Xl[128*GS], Wh[128*GS], Wl[128*GS];
    const int tid = threadIdx.x;
    const int lane = tid & 31;
    const int wid = tid >> 5;
    const int g = lane >> 2, tig = lane & 3;
    const int wm = wid >> 2, wn = wid & 3;
    const int m0 = blockIdx.y * 128, n0 = blockIdx.x * 128;
    const int N = Dq, K = Dq;

    int lrow[2], lcol[2];
#pragma unroll
    for (int it = 0; it < 2; it++) {
        int idx = tid + 256 * it;
        lrow[it] = idx >> 2;
        lcol[it] = (idx & 3) * 4;
    }

    float4 xr[2], wr[2];
#pragma unroll
    for (int it = 0; it < 2; it++) {
        xr[it] = *(const float4*)(X + (size_t)(m0 + lrow[it]) * K + lcol[it]);
        wr[it] = *(const float4*)(W + (size_t)(n0 + lrow[it]) * K + lcol[it]);
    }

    float acc[4][4][4];
#pragma unroll
    for (int i = 0; i < 4; i++)
#pragma unroll
        for (int j = 0; j < 4; j++)
#pragma unroll
            for (int r = 0; r < 4; r++) acc[i][j][r] = 0.f;

    for (int k0 = 0; k0 < K; k0 += 16) {
        __syncthreads();
#pragma unroll
        for (int it = 0; it < 2; it++) {
            int r = lrow[it], p = lcol[it] >> 1;
            split2(xr[it].x, xr[it].y, Xh[r*GS + p],     Xl[r*GS + p]);
            split2(xr[it].z, xr[it].w, Xh[r*GS + p + 1], Xl[r*GS + p + 1]);
            split2(wr[it].x, wr[it].y, Wh[r*GS + p],     Wl[r*GS + p]);
            split2(wr[it].z, wr[it].w, Wh[r*GS + p + 1], Wl[r*GS + p + 1]);
        }
        if (k0 + 16 < K) {
#pragma unroll
            for (int it = 0; it < 2; it++) {
                xr[it] = *(const float4*)(X + (size_t)(m0 + lrow[it]) * K + k0 + 16 + lcol[it]);
                wr[it] = *(const float4*)(W + (size_t)(n0 + lrow[it]) * K + k0 + 16 + lcol[it]);
            }
        }
        __syncthreads();

        uint32_t ah[4][4], al[4][4];
#pragma unroll
        for (int i = 0; i < 4; i++) {
            int r0 = (wm*64 + 16*i + g) * GS;
            int r8 = r0 + 8*GS;
            ah[i][0] = Xh[r0 + tig];     ah[i][1] = Xh[r8 + tig];
            ah[i][2] = Xh[r0 + tig + 4]; ah[i][3] = Xh[r8 + tig + 4];
            al[i][0] = Xl[r0 + tig];     al[i][1] = Xl[r8 + tig];
            al[i][2] = Xl[r0 + tig + 4]; al[i][3] = Xl[r8 + tig + 4];
        }
#pragma unroll
        for (int j = 0; j < 4; j++) {
            int rb = (wn*32 + 8*j + g) * GS;
            uint32_t bh0 = Wh[rb + tig], bh1 = Wh[rb + tig + 4];
            uint32_t bl0 = Wl[rb + tig], bl1 = Wl[rb + tig + 4];
#pragma unroll
            for (int i = 0; i < 4; i++) {
                mma16816(acc[i][j], ah[i], bh0, bh1);
                mma16816(acc[i][j], ah[i], bl0, bl1);
                mma16816(acc[i][j], al[i], bh0, bh1);
            }
        }
    }

#pragma unroll
    for (int j = 0; j < 4; j++) {
        int cc = n0 + wn*32 + 8*j + 2*tig;
        float b0 = bias[cc], b1 = bias[cc + 1];
#pragma unroll
        for (int i = 0; i < 4; i++) {
            int rr = m0 + wm*64 + 16*i + g;
            float2 v0 = make_float2(acc[i][j][0] + b0, acc[i][j][1] + b1);
            float2 v1 = make_float2(acc[i][j][2] + b0, acc[i][j][3] + b1);
            *(float2*)(O + (size_t)rr * N + cc) = v0;
            *(float2*)(O + (size_t)(rr + 8) * N + cc) = v1;
        }
    }
}

// ---------------------------------------------------------------------------
// Flash attention, bf16x3 mma. 128 q-rows/CTA, 8 warps x 16 q-rows,
// 64-key KV tiles, score fragments reused directly as PV A-fragments.
// smem pair-row stride AS=36 (conflict-free: 36g ≡ 4g mod 32)
// ---------------------------------------------------------------------------
#define AS 36
#define QH_OFF 0
#define QL_OFF (128*AS)
#define KH_OFF (2*128*AS)
#define KL_OFF (KH_OFF + 64*AS)
#define VH_OFF (KL_OFF + 64*AS)
#define VL_OFF (VH_OFF + 64*AS)
#define MS_OFF (VL_OFF + 64*AS)
#define SMEM_U32 (MS_OFF + 64)

__global__ void __launch_bounds__(256) attn_kernel(
    const float* __restrict__ Q, const float* __restrict__ K,
    const float* __restrict__ V, const float* __restrict__ mask,
    float* __restrict__ Ctx)
{
    extern __shared__ uint32_t sm[];
    float* msf = reinterpret_cast<float*>(sm + MS_OFF);

    const int tid = threadIdx.x;
    const int lane = tid & 31;
    const int wid = tid >> 5;
    const int g = lane >> 2, tig = lane & 3;
    const int bh = blockIdx.y;
    const int b = bh >> 4, h = bh & 15;
    const int q0 = blockIdx.x * 128;

    const size_t baseQ  = ((size_t)(b * Sq + q0)) * Dq + h * HDq;
    const size_t baseKV = ((size_t)(b * Sq)) * Dq + h * HDq;

    // Load Q tile (scale 1/8 folded), split into bf16 hi/lo pair layout
#pragma unroll
    for (int it = 0; it < 8; it++) {
        int idx = tid + 256 * it;
        int r = idx >> 4, c4 = (idx & 15) * 4;
        float4 qv = *(const float4*)(Q + baseQ + (size_t)r * Dq + c4);
        int p = r * AS + (c4 >> 1);
        split2(qv.x * 0.125f, qv.y * 0.125f, sm[QH_OFF + p],     sm[QL_OFF + p]);
        split2(qv.z * 0.125f, qv.w * 0.125f, sm[QH_OFF + p + 1], sm[QL_OFF + p + 1]);
    }

    float m0r = -1e30f, m1r = -1e30f, l0 = 0.f, l1 = 0.f;
    float o[8][4];
#pragma unroll
    for (int jj = 0; jj < 8; jj++)
#pragma unroll
        for (int r = 0; r < 4; r++) o[jj][r] = 0.f;

    for (int k0 = 0; k0 < Sq; k0 += 64) {
        __syncthreads();
        // K: natural [key][hd] pairs; V: transposed [hd][key] bf16 scalars
#pragma unroll
        for (int it = 0; it < 4; it++) {
            int idx = tid + 256 * it;
            int r = idx >> 4, c4 = (idx & 15) * 4;
            float4 kv = *(const float4*)(K + baseKV + (size_t)(k0 + r) * Dq + c4);
            float4 vv = *(const float4*)(V + baseKV + (size_t)(k0 + r) * Dq + c4);
            int p = r * AS + (c4 >> 1);
            split2(kv.x, kv.y, sm[KH_OFF + p],     sm[KL_OFF + p]);
            split2(kv.z, kv.w, sm[KH_OFF + p + 1], sm[KL_OFF + p + 1]);
            __nv_bfloat16* vh = reinterpret_cast<__nv_bfloat16*>(sm + VH_OFF);
            __nv_bfloat16* vl = reinterpret_cast<__nv_bfloat16*>(sm + VL_OFF);
            float ve[4] = {vv.x, vv.y, vv.z, vv.w};
#pragma unroll
            for (int e = 0; e < 4; e++) {
                __nv_bfloat16 hv = __float2bfloat16_rn(ve[e]);
                vh[(c4 + e) * (2*AS) + r] = hv;
                vl[(c4 + e) * (2*AS) + r] =
                    __float2bfloat16_rn(ve[e] - __bfloat162float(hv));
            }
        }
        if (tid < 64) msf[tid] = mask[b * Sq + k0 + tid];
        __syncthreads();

        // ---- S = Q K^T ----
        float s[8][4];
#pragma unroll
        for (int j = 0; j < 8; j++)
#pragma unroll
            for (int r = 0; r < 4; r++) s[j][r] = 0.f;

#pragma unroll
        for (int kb = 0; kb < 4; kb++) {
            int r0 = (16*wid + g) * AS + kb*8;
            int r8 = r0 + 8*AS;
            uint32_t ah[4], al[4];
            ah[0] = sm[QH_OFF + r0 + tig];     ah[1] = sm[QH_OFF + r8 + tig];
            ah[2] = sm[QH_OFF + r0 + tig + 4]; ah[3] = sm[QH_OFF + r8 + tig + 4];
            al[0] = sm[QL_OFF + r0 + tig];     al[1] = sm[QL_OFF + r8 + tig];
            al[2] = sm[QL_OFF + r0 + tig + 4]; al[3] = sm[QL_OFF + r8 + tig + 4];
#pragma unroll
            for (int j = 0; j < 8; j++) {
                int rb = (8*j + g) * AS + kb*8;
                uint32_t bh0 = sm[KH_OFF + rb + tig], bh1 = sm[KH_OFF + rb + tig + 4];
                uint32_t bl0 = sm[KL_OFF + rb + tig], bl1 = sm[KL_OFF + rb + tig + 4];
                mma16816(s[j], ah, bh0, bh1);
                mma16816(s[j], ah, bl0, bl1);
                mma16816(s[j], al, bh0, bh1);
            }
        }

        // ---- mask + online softmax ----
        float mx0 = -1e30f, mx1 = -1e30f;
#pragma unroll
        for (int j = 0; j < 8; j++) {
            float mk0 = msf[8*j + 2*tig], mk1 = msf[8*j + 2*tig + 1];
            s[j][0] += mk0; s[j][1] += mk1;
            s[j][2] += mk0; s[j][3] += mk1;
            mx0 = fmaxf(mx0, fmaxf(s[j][0], s[j][1]));
            mx1 = fmaxf(mx1, fmaxf(s[j][2], s[j][3]));
        }
        mx0 = fmaxf(mx0, __shfl_xor_sync(0xffffffffu, mx0, 1));
        mx0 = fmaxf(mx0, __shfl_xor_sync(0xffffffffu, mx0, 2));
        mx1 = fmaxf(mx1, __shfl_xor_sync(0xffffffffu, mx1, 1));
        mx1 = fmaxf(mx1, __shfl_xor_sync(0xffffffffu, mx1, 2));
        float mn0 = fmaxf(m0r, mx0), mn1 = fmaxf(m1r, mx1);
        float al0 = __expf(m0r - mn0), al1 = __expf(m1r - mn1);
        m0r = mn0; m1r = mn1;
        float sum0 = 0.f, sum1 = 0.f;
#pragma unroll
        for (int j = 0; j < 8; j++) {
            s[j][0] = __expf(s[j][0] - mn0); sum0 += s[j][0];
            s[j][1] = __expf(s[j][1] - mn0); sum0 += s[j][1];
            s[j][2] = __expf(s[j][2] - mn1); sum1 += s[j][2];
            s[j][3] = __expf(s[j][3] - mn1); sum1 += s[j][3];
        }
        sum0 += __shfl_xor_sync(0xffffffffu, sum0, 1);
        sum0 += __shfl_xor_sync(0xffffffffu, sum0, 2);
        sum1 += __shfl_xor_sync(0xffffffffu, sum1, 1);
        sum1 += __shfl_xor_sync(0xffffffffu, sum1, 2);
        l0 = l0 * al0 + sum0;
        l1 = l1 * al1 + sum1;
#pragma unroll
        for (int jj = 0; jj < 8; jj++) {
            o[jj][0] *= al0; o[jj][1] *= al0;
            o[jj][2] *= al1; o[jj][3] *= al1;
        }

        // ---- pack P (scores) as PV A-fragments, hi/lo ----
        uint32_t ph[4][4], pl[4][4];
#pragma unroll
        for (int kb = 0; kb < 4; kb++) {
            split2(s[2*kb][0],   s[2*kb][1],   ph[kb][0], pl[kb][0]);
            split2(s[2*kb][2],   s[2*kb][3],   ph[kb][1], pl[kb][1]);
            split2(s[2*kb+1][0], s[2*kb+1][1], ph[kb][2], pl[kb][2]);
            split2(s[2*kb+1][2], s[2*kb+1][3], ph[kb][3], pl[kb][3]);
        }

        // ---- O += P V ----
#pragma unroll
        for (int kb = 0; kb < 4; kb++) {
#pragma unroll
            for (int jj = 0; jj < 8; jj++) {
                int rv = (8*jj + g) * AS + kb*8;
                uint32_t vh0 = sm[VH_OFF + rv + tig], vh1 = sm[VH_OFF + rv + tig + 4];
                uint32_t vl0 = sm[VL_OFF + rv + tig], vl1 = sm[VL_OFF + rv + tig + 4];
                mma16816(o[jj], ph[kb], vh0, vh1);
                mma16816(o[jj], ph[kb], vl0, vl1);
                mma16816(o[jj], pl[kb], vh0, vh1);
            }
        }
    }

    float inv0 = 1.0f / l0, inv1 = 1.0f / l1;
    size_t base = ((size_t)(b * Sq + q0 + 16*wid + g)) * Dq + h * HDq;
#pragma unroll
    for (int jj = 0; jj < 8; jj++) {
        int cc = 8*jj + 2*tig;
        float2 v0 = make_float2(o[jj][0] * inv0, o[jj][1] * inv0);
        float2 v1 = make_float2(o[jj][2] * inv1, o[jj][3] * inv1);
        *(float2*)(Ctx + base + cc) = v0;
        *(float2*)(Ctx + base + 8 * Dq + cc) = v1;
    }
}

// ---------------------------------------------------------------------------

extern "C" void kernel_launch(void* const* d_in, const int* in_sizes, int n_in,
                              void* d_out, int out_size)
{
    const float* hs   = (const float*)d_in[0];
    const float* mask = (const float*)d_in[1];
    const float* Wq   = (const float*)d_in[2];
    const float* bq   = (const float*)d_in[3];
    const float* Wk   = (const float*)d_in[4];
    const float* bk   = (const float*)d_in[5];
    const float* Wv   = (const float*)d_in[6];
    const float* bv   = (const float*)d_in[7];
    const float* Wo   = (const float*)d_in[8];
    const float* bo   = (const float*)d_in[9];
    float* out = (float*)d_out;

    float *q, *k, *v, *c;
    cudaGetSymbolAddress((void**)&q, g_Q);
    cudaGetSymbolAddress((void**)&k, g_K);
    cudaGetSymbolAddress((void**)&v, g_V);
    cudaGetSymbolAddress((void**)&c, g_C);

    dim3 ggrid(Dq / 128, Mq / 128);
    gemm_kernel<<<ggrid, 256>>>(hs, Wq, bq, q);
    gemm_kernel<<<ggrid, 256>>>(hs, Wk, bk, k);
    gemm_kernel<<<ggrid, 256>>>(hs, Wv, bv, v);

    size_t smem = SMEM_U32 * sizeof(uint32_t);
    cudaFuncSetAttribute(attn_kernel,
                         cudaFuncAttributeMaxDynamicSharedMemorySize, (int)smem);
    dim3 agrid(Sq / 128, Bq * Hq);
    attn_kernel<<<agrid, 256, smem>>>(q, k, v, mask, c);

    gemm_kernel<<<ggrid, 256>>>(c, Wo, bo, out);
}

// round 4
// speedup vs baseline: 3.1080x; 1.4084x over previous
#include <cuda_runtime.h>
#include <cuda_bf16.h>
#include <cstdint>

#define Bq 2
#define Sq 2048
#define Dq 1024
#define Hq 16
#define HDq 64
#define Mq (Bq*Sq)

// ---------------- global scratch (allocation-free) ----------------
__device__ __align__(16) __nv_bfloat16 gXh[Mq*Dq], gXl[Mq*Dq];
__device__ __align__(16) __nv_bfloat16 gWh[4][Dq*Dq], gWl[4][Dq*Dq];
__device__ __align__(16) __nv_bfloat16 gQh[Mq*Dq], gQl[Mq*Dq];
__device__ __align__(16) __nv_bfloat16 gKh[Mq*Dq], gKl[Mq*Dq];
__device__ __align__(16) __nv_bfloat16 gVh[Mq*Dq], gVl[Mq*Dq];
__device__ __align__(16) __nv_bfloat16 gCh[Mq*Dq], gCl[Mq*Dq];

// ---------------- small helpers ----------------
__device__ __forceinline__ void split2(float x, float y,
                                       uint32_t& hi, uint32_t& lo) {
    __nv_bfloat16 hx = __float2bfloat16_rn(x);
    __nv_bfloat16 hy = __float2bfloat16_rn(y);
    __nv_bfloat162 h2 = __halves2bfloat162(hx, hy);
    __nv_bfloat162 l2 = __halves2bfloat162(
        __float2bfloat16_rn(x - __bfloat162float(hx)),
        __float2bfloat16_rn(y - __bfloat162float(hy)));
    hi = *reinterpret_cast<uint32_t*>(&h2);
    lo = *reinterpret_cast<uint32_t*>(&l2);
}

__device__ __forceinline__ void mma16816(float* c, const uint32_t* a,
                                         uint32_t b0, uint32_t b1) {
    asm volatile("mma.sync.aligned.m16n8k16.row.col.f32.bf16.bf16.f32 "
                 "{%0,%1,%2,%3}, {%4,%5,%6,%7}, {%8,%9}, {%0,%1,%2,%3};"
                 : "+f"(c[0]), "+f"(c[1]), "+f"(c[2]), "+f"(c[3])
                 : "r"(a[0]), "r"(a[1]), "r"(a[2]), "r"(a[3]),
                   "r"(b0), "r"(b1));
}

__device__ __forceinline__ void ldm_x4(uint32_t* r, uint32_t a) {
    asm volatile("ldmatrix.sync.aligned.m8n8.x4.shared.b16 {%0,%1,%2,%3}, [%4];"
                 : "=r"(r[0]), "=r"(r[1]), "=r"(r[2]), "=r"(r[3]) : "r"(a));
}
__device__ __forceinline__ void ldm_x4_t(uint32_t* r, uint32_t a) {
    asm volatile("ldmatrix.sync.aligned.m8n8.x4.trans.shared.b16 {%0,%1,%2,%3}, [%4];"
                 : "=r"(r[0]), "=r"(r[1]), "=r"(r[2]), "=r"(r[3]) : "r"(a));
}

__device__ __forceinline__ uint32_t smem_u32(const void* p) {
    uint32_t a;
    asm("{ .reg .u64 t; cvta.to.shared.u64 t, %1; cvt.u32.u64 %0, t; }"
        : "=r"(a) : "l"(p));
    return a;
}

__device__ __forceinline__ void cp16(uint32_t dst, const void* src) {
    asm volatile("cp.async.cg.shared.global [%0], [%1], 16;" :: "r"(dst), "l"(src));
}

// ---------------------------------------------------------------------------
// split kernel: f32 -> bf16 hi/lo (optionally scaled by exact power of two)
// ---------------------------------------------------------------------------
__global__ void split_kernel(const float* __restrict__ src,
                             __nv_bfloat16* __restrict__ hi,
                             __nv_bfloat16* __restrict__ lo,
                             int n4, float scale)
{
    int i = blockIdx.x * blockDim.x + threadIdx.x;
    if (i >= n4) return;
    float4 v = ((const float4*)src)[i];
    uint32_t h0, l0, h1, l1;
    split2(v.x * scale, v.y * scale, h0, l0);
    split2(v.z * scale, v.w * scale, h1, l1);
    ((uint2*)hi)[i] = make_uint2(h0, h1);
    ((uint2*)lo)[i] = make_uint2(l0, l1);
}

// ---------------------------------------------------------------------------
// bf16x3 GEMM, mma.sync + ldmatrix + cp.async double buffering.
// O[m,n] = sum_k (Ah+Al)[m,k]*(Bh+Bl)[n,k] + bias[n]*bscale
// 128x128 CTA tile, BK=32, 256 thr, warp tile 64x32 (2x4 warp grid).
// smem rows: 32 bf16 = 64B data, stride 80B (conflict-free for cp.async
// 16B stores and ldmatrix 8-row phases: r*20 words mod 32 all distinct).
// ---------------------------------------------------------------------------
#define GST 80
#define ATB (128*GST)          // 10240 bytes per array tile
#define STAGE_B (4*ATB)        // Ah,Al,Bh,Bl
#define GEMM_SMEM (2*STAGE_B)  // 81920

__global__ void __launch_bounds__(256) gemm_tc(
    const __nv_bfloat16* __restrict__ Ah, const __nv_bfloat16* __restrict__ Al,
    const __nv_bfloat16* __restrict__ Bh, const __nv_bfloat16* __restrict__ Bl,
    const float* __restrict__ bias, float bscale,
    float* __restrict__ outF,
    __nv_bfloat16* __restrict__ outH, __nv_bfloat16* __restrict__ outL,
    int writeF)
{
    extern __shared__ char smem[];
    const uint32_t sb = smem_u32(smem);
    const int tid = threadIdx.x;
    const int wid = tid >> 5, lane = tid & 31;
    const int g = lane >> 2, tig = lane & 3;
    const int q4 = lane >> 3, m8 = lane & 7;
    const int wm = wid & 1, wn = wid >> 1;
    const int m0 = blockIdx.y * 128, n0 = blockIdx.x * 128;

    // loader role: each 64-thread group owns one array
    const int grp = tid >> 6, tg = tid & 63;
    const __nv_bfloat16* msrc =
        (grp == 0) ? Ah + (size_t)m0 * Dq :
        (grp == 1) ? Al + (size_t)m0 * Dq :
        (grp == 2) ? Bh + (size_t)n0 * Dq : Bl + (size_t)n0 * Dq;
    const uint32_t aoff = grp * ATB;

    // per-lane ldmatrix bases (relative to stage base)
    // A (row-major m x k): lanes -> rows 0-15, 16B col chunks
    const uint32_t aRel = (uint32_t)((wm*64 + ((q4&1)<<3) + m8) * GST + ((q4>>1)<<4));
    // B (n-rows x k): lanes -> n rows 0-7/8-15, 16B col chunks
    const uint32_t bRel = (uint32_t)(2*ATB + (wn*32 + ((q4>>1)<<3) + m8) * GST + ((q4&1)<<4));

    float acc[4][4][4];
#pragma unroll
    for (int i = 0; i < 4; i++)
#pragma unroll
        for (int j = 0; j < 4; j++)
#pragma unroll
            for (int r = 0; r < 4; r++) acc[i][j][r] = 0.f;

    // prefetch stage 0
    {
        const uint32_t stage = sb;
#pragma unroll
        for (int i = 0; i < 8; i++) {
            int chunk = tg + 64 * i;
            int r = chunk >> 2, c = chunk & 3;
            cp16(stage + aoff + r * GST + c * 16, msrc + (size_t)r * Dq + c * 8);
        }
        asm volatile("cp.async.commit_group;" ::: "memory");
    }

    for (int it = 0; it < 32; it++) {
        const int buf = it & 1;
        const uint32_t stage = sb + buf * STAGE_B;
        if (it < 31) {
            const uint32_t nstage = sb + (buf ^ 1) * STAGE_B;
            const int k0 = (it + 1) * 32;
#pragma unroll
            for (int i = 0; i < 8; i++) {
                int chunk = tg + 64 * i;
                int r = chunk >> 2, c = chunk & 3;
                cp16(nstage + aoff + r * GST + c * 16,
                     msrc + (size_t)r * Dq + k0 + c * 8);
            }
            asm volatile("cp.async.commit_group;" ::: "memory");
            asm volatile("cp.async.wait_group 1;" ::: "memory");
        } else {
            asm volatile("cp.async.wait_group 0;" ::: "memory");
        }
        __syncthreads();

#pragma unroll
        for (int ks = 0; ks < 2; ks++) {
            uint32_t ah[4][4], al[4][4];
#pragma unroll
            for (int i = 0; i < 4; i++) {
                ldm_x4(ah[i], stage + aRel + i * (16*GST) + ks * 32);
                ldm_x4(al[i], stage + ATB + aRel + i * (16*GST) + ks * 32);
            }
#pragma unroll
            for (int jb = 0; jb < 2; jb++) {
                uint32_t bH[4], bL[4];
                ldm_x4(bH, stage + bRel + jb * (16*GST) + ks * 32);
                ldm_x4(bL, stage + ATB + bRel + jb * (16*GST) + ks * 32);
#pragma unroll
                for (int i = 0; i < 4; i++) {
                    mma16816(acc[i][2*jb],   ah[i], bH[0], bH[1]);
                    mma16816(acc[i][2*jb],   ah[i], bL[0], bL[1]);
                    mma16816(acc[i][2*jb],   al[i], bH[0], bH[1]);
                    mma16816(acc[i][2*jb+1], ah[i], bH[2], bH[3]);
                    mma16816(acc[i][2*jb+1], ah[i], bL[2], bL[3]);
                    mma16816(acc[i][2*jb+1], al[i], bH[2], bH[3]);
                }
            }
        }
        __syncthreads();
    }

    // epilogue
#pragma unroll
    for (int j = 0; j < 4; j++) {
        int cc = n0 + wn*32 + 8*j + 2*tig;
        float b0 = bias[cc] * bscale, b1 = bias[cc + 1] * bscale;
#pragma unroll
        for (int i = 0; i < 4; i++) {
            int rr = m0 + wm*64 + 16*i + g;
            float v00 = acc[i][j][0] + b0, v01 = acc[i][j][1] + b1;
            float v10 = acc[i][j][2] + b0, v11 = acc[i][j][3] + b1;
            if (writeF) {
                *(float2*)(outF + (size_t)rr * Dq + cc) = make_float2(v00, v01);
                *(float2*)(outF + (size_t)(rr + 8) * Dq + cc) = make_float2(v10, v11);
            } else {
                uint32_t h0, l0, h1, l1;
                split2(v00, v01, h0, l0);
                split2(v10, v11, h1, l1);
                size_t i0 = ((size_t)rr * Dq + cc) >> 1;
                size_t i1 = ((size_t)(rr + 8) * Dq + cc) >> 1;
                ((uint32_t*)outH)[i0] = h0; ((uint32_t*)outL)[i0] = l0;
                ((uint32_t*)outH)[i1] = h1; ((uint32_t*)outL)[i1] = l1;
            }
        }
    }
}

// ---------------------------------------------------------------------------
// Flash attention, bf16x3 mma.sync + ldmatrix fragments.
// 128 q-rows/CTA (8 warps x 16), 64-key tiles. Q/K/V natural bf16 rows,
// row stride 144B (conflict-free ldmatrix). V fragments via ldmatrix.trans.
// Scale 1/8 pre-folded into Wq. Outputs ctx as bf16 hi/lo.
// ---------------------------------------------------------------------------
#define QH_B 0
#define QL_B 18432
#define KH_B 36864
#define KL_B 46080
#define VH_B 55296
#define VL_B 64512
#define MS_B 73728
#define ATT_SMEM 73984

__global__ void __launch_bounds__(256, 2) attn_kernel(
    const __nv_bfloat16* __restrict__ Qh, const __nv_bfloat16* __restrict__ Ql,
    const __nv_bfloat16* __restrict__ Kh, const __nv_bfloat16* __restrict__ Kl,
    const __nv_bfloat16* __restrict__ Vh, const __nv_bfloat16* __restrict__ Vl,
    const float* __restrict__ mask,
    __nv_bfloat16* __restrict__ Ch, __nv_bfloat16* __restrict__ Cl)
{
    extern __shared__ char smem[];
    const uint32_t sbB = smem_u32(smem);
    float* msf = reinterpret_cast<float*>(smem + MS_B);

    const int tid = threadIdx.x;
    const int lane = tid & 31;
    const int wid = tid >> 5;
    const int g = lane >> 2, tig = lane & 3;
    const int bh = blockIdx.y;
    const int b = bh >> 4, h = bh & 15;
    const int q0 = blockIdx.x * 128;

    const size_t baseQ  = ((size_t)(b * Sq + q0)) * Dq + h * HDq;
    const size_t baseKV = ((size_t)(b * Sq)) * Dq + h * HDq;

    // per-lane ldmatrix address bases
    const int q4 = lane >> 3, m8 = lane & 7;
    const uint32_t aHb = sbB + QH_B + (16*wid + ((q4&1)<<3) + m8)*144 + ((q4>>1)<<4);
    const uint32_t aLb = aHb + (QL_B - QH_B);
    const uint32_t kHb = sbB + KH_B + (((q4>>1)<<3) + m8)*144 + ((q4&1)<<4);
    const uint32_t kLb = kHb + (KL_B - KH_B);
    const uint32_t vHb = sbB + VH_B + (((q4&1)<<3) + m8)*144 + ((q4>>1)<<4);
    const uint32_t vLb = vHb + (VL_B - VH_B);

    // ---- load Q tile (hi/lo), natural rows ----
    {
        const int hg = tid >> 7, ht = tid & 127;   // hg: 0=hi,1=lo
        const __nv_bfloat16* src = hg ? Ql : Qh;
        const uint32_t off = hg ? QL_B : QH_B;
#pragma unroll
        for (int i = 0; i < 8; i++) {
            int chunk = ht + 128 * i;               // 1024 chunks per array
            int r = chunk >> 3, c = chunk & 7;
            uint4 v = ((const uint4*)(src + baseQ + (size_t)r * Dq))[c];
            *(uint4*)(smem + off + r * 144 + c * 16) = v;
        }
    }

    float m0r = -1e30f, m1r = -1e30f, l0 = 0.f, l1 = 0.f;
    float o[8][4];
#pragma unroll
    for (int jj = 0; jj < 8; jj++)
#pragma unroll
        for (int r = 0; r < 4; r++) o[jj][r] = 0.f;

    const int grp = tid >> 6, tg = tid & 63;
    const __nv_bfloat16* kvsrc = (grp==0) ? Kh : (grp==1) ? Kl : (grp==2) ? Vh : Vl;
    const uint32_t kvoff = (grp==0) ? KH_B : (grp==1) ? KL_B : (grp==2) ? VH_B : VL_B;

    for (int k0 = 0; k0 < Sq; k0 += 64) {
        __syncthreads();
#pragma unroll
        for (int i = 0; i < 8; i++) {
            int chunk = tg + 64 * i;                // 512 chunks per array
            int r = chunk >> 3, c = chunk & 7;
            uint4 v = ((const uint4*)(kvsrc + baseKV + (size_t)(k0 + r) * Dq))[c];
            *(uint4*)(smem + kvoff + r * 144 + c * 16) = v;
        }
        if (tid < 64) msf[tid] = mask[b * Sq + k0 + tid];
        __syncthreads();

        // ---- S = Q K^T ----
        float s[8][4];
#pragma unroll
        for (int j = 0; j < 8; j++)
#pragma unroll
            for (int r = 0; r < 4; r++) s[j][r] = 0.f;

#pragma unroll
        for (int kb = 0; kb < 4; kb++) {
            uint32_t aH[4], aL[4];
            ldm_x4(aH, aHb + kb * 32);
            ldm_x4(aL, aLb + kb * 32);
#pragma unroll
            for (int jp = 0; jp < 4; jp++) {
                uint32_t bH[4], bL[4];
                ldm_x4(bH, kHb + jp * 2304 + kb * 32);
                ldm_x4(bL, kLb + jp * 2304 + kb * 32);
                mma16816(s[2*jp],   aH, bH[0], bH[1]);
                mma16816(s[2*jp],   aH, bL[0], bL[1]);
                mma16816(s[2*jp],   aL, bH[0], bH[1]);
                mma16816(s[2*jp+1], aH, bH[2], bH[3]);
                mma16816(s[2*jp+1], aH, bL[2], bL[3]);
                mma16816(s[2*jp+1], aL, bH[2], bH[3]);
            }
        }

        // ---- mask + online softmax ----
        float mx0 = -1e30f, mx1 = -1e30f;
#pragma unroll
        for (int j = 0; j < 8; j++) {
            float mk0 = msf[8*j + 2*tig], mk1 = msf[8*j + 2*tig + 1];
            s[j][0] += mk0; s[j][1] += mk1;
            s[j][2] += mk0; s[j][3] += mk1;
            mx0 = fmaxf(mx0, fmaxf(s[j][0], s[j][1]));
            mx1 = fmaxf(mx1, fmaxf(s[j][2], s[j][3]));
        }
        mx0 = fmaxf(mx0, __shfl_xor_sync(0xffffffffu, mx0, 1));
        mx0 = fmaxf(mx0, __shfl_xor_sync(0xffffffffu, mx0, 2));
        mx1 = fmaxf(mx1, __shfl_xor_sync(0xffffffffu, mx1, 1));
        mx1 = fmaxf(mx1, __shfl_xor_sync(0xffffffffu, mx1, 2));
        float mn0 = fmaxf(m0r, mx0), mn1 = fmaxf(m1r, mx1);
        float al0 = __expf(m0r - mn0), al1 = __expf(m1r - mn1);
        m0r = mn0; m1r = mn1;
        float sum0 = 0.f, sum1 = 0.f;
#pragma unroll
        for (int j = 0; j < 8; j++) {
            s[j][0] = __expf(s[j][0] - mn0); sum0 += s[j][0];
            s[j][1] = __expf(s[j][1] - mn0); sum0 += s[j][1];
            s[j][2] = __expf(s[j][2] - mn1); sum1 += s[j][2];
            s[j][3] = __expf(s[j][3] - mn1); sum1 += s[j][3];
        }
        sum0 += __shfl_xor_sync(0xffffffffu, sum0, 1);
        sum0 += __shfl_xor_sync(0xffffffffu, sum0, 2);
        sum1 += __shfl_xor_sync(0xffffffffu, sum1, 1);
        sum1 += __shfl_xor_sync(0xffffffffu, sum1, 2);
        l0 = l0 * al0 + sum0;
        l1 = l1 * al1 + sum1;
#pragma unroll
        for (int jj = 0; jj < 8; jj++) {
            o[jj][0] *= al0; o[jj][1] *= al0;
            o[jj][2] *= al1; o[jj][3] *= al1;
        }

        // ---- pack P as PV A-fragments (hi/lo) ----
        uint32_t ph[4][4], pl[4][4];
#pragma unroll
        for (int kb = 0; kb < 4; kb++) {
            split2(s[2*kb][0],   s[2*kb][1],   ph[kb][0], pl[kb][0]);
            split2(s[2*kb][2],   s[2*kb][3],   ph[kb][1], pl[kb][1]);
            split2(s[2*kb+1][0], s[2*kb+1][1], ph[kb][2], pl[kb][2]);
            split2(s[2*kb+1][2], s[2*kb+1][3], ph[kb][3], pl[kb][3]);
        }

        // ---- O += P V  (V fragments via ldmatrix.trans) ----
#pragma unroll
        for (int kb = 0; kb < 4; kb++) {
#pragma unroll
            for (int jp = 0; jp < 4; jp++) {
                uint32_t vH[4], vL[4];
                ldm_x4_t(vH, vHb + kb * 2304 + jp * 32);
                ldm_x4_t(vL, vLb + kb * 2304 + jp * 32);
                mma16816(o[2*jp],   ph[kb], vH[0], vH[1]);
                mma16816(o[2*jp],   ph[kb], vL[0], vL[1]);
                mma16816(o[2*jp],   pl[kb], vH[0], vH[1]);
                mma16816(o[2*jp+1], ph[kb], vH[2], vH[3]);
                mma16816(o[2*jp+1], ph[kb], vL[2], vL[3]);
                mma16816(o[2*jp+1], pl[kb], vH[2], vH[3]);
            }
        }
    }

    // ---- epilogue: ctx as bf16 hi/lo ----
    float inv0 = 1.0f / l0, inv1 = 1.0f / l1;
    size_t row0 = (size_t)(b * Sq + q0 + 16*wid + g);
#pragma unroll
    for (int jj = 0; jj < 8; jj++) {
        int cc = 8*jj + 2*tig;
        uint32_t h0, l0b, h1, l1b;
        split2(o[jj][0] * inv0, o[jj][1] * inv0, h0, l0b);
        split2(o[jj][2] * inv1, o[jj][3] * inv1, h1, l1b);
        size_t i0 = (row0 * Dq + h * HDq + cc) >> 1;
        size_t i1 = ((row0 + 8) * Dq + h * HDq + cc) >> 1;
        ((uint32_t*)Ch)[i0] = h0; ((uint32_t*)Cl)[i0] = l0b;
        ((uint32_t*)Ch)[i1] = h1; ((uint32_t*)Cl)[i1] = l1b;
    }
}

// ---------------------------------------------------------------------------

extern "C" void kernel_launch(void* const* d_in, const int* in_sizes, int n_in,
                              void* d_out, int out_size)
{
    const float* hs   = (const float*)d_in[0];
    const float* mask = (const float*)d_in[1];
    const float* Wq   = (const float*)d_in[2];
    const float* bq   = (const float*)d_in[3];
    const float* Wk   = (const float*)d_in[4];
    const float* bk   = (const float*)d_in[5];
    const float* Wv   = (const float*)d_in[6];
    const float* bv   = (const float*)d_in[7];
    const float* Wo   = (const float*)d_in[8];
    const float* bo   = (const float*)d_in[9];
    float* out = (float*)d_out;

    __nv_bfloat16 *xh, *xl, *wh, *wl, *qh, *ql, *kh, *kl, *vh, *vl, *ch, *cl;
    cudaGetSymbolAddress((void**)&xh, gXh); cudaGetSymbolAddress((void**)&xl, gXl);
    cudaGetSymbolAddress((void**)&wh, gWh); cudaGetSymbolAddress((void**)&wl, gWl);
    cudaGetSymbolAddress((void**)&qh, gQh); cudaGetSymbolAddress((void**)&ql, gQl);
    cudaGetSymbolAddress((void**)&kh, gKh); cudaGetSymbolAddress((void**)&kl, gKl);
    cudaGetSymbolAddress((void**)&vh, gVh); cudaGetSymbolAddress((void**)&vl, gVl);
    cudaGetSymbolAddress((void**)&ch, gCh); cudaGetSymbolAddress((void**)&cl, gCl);

    const int WN = Dq * Dq;   // elems per weight matrix

    // splits (scale 1/8 folded into Wq)
    split_kernel<<<(Mq*Dq/4 + 255)/256, 256>>>(hs, xh, xl, Mq*Dq/4, 1.0f);
    split_kernel<<<(WN/4 + 255)/256, 256>>>(Wq, wh + 0*WN, wl + 0*WN, WN/4, 0.125f);
    split_kernel<<<(WN/4 + 255)/256, 256>>>(Wk, wh + 1*WN, wl + 1*WN, WN/4, 1.0f);
    split_kernel<<<(WN/4 + 255)/256, 256>>>(Wv, wh + 2*WN, wl + 2*WN, WN/4, 1.0f);
    split_kernel<<<(WN/4 + 255)/256, 256>>>(Wo, wh + 3*WN, wl + 3*WN, WN/4, 1.0f);

    cudaFuncSetAttribute(gemm_tc, cudaFuncAttributeMaxDynamicSharedMemorySize, GEMM_SMEM);
    dim3 ggrid(Dq / 128, Mq / 128);

    gemm_tc<<<ggrid, 256, GEMM_SMEM>>>(xh, xl, wh + 0*WN, wl + 0*WN, bq, 0.125f,
                                       nullptr, qh, ql, 0);
    gemm_tc<<<ggrid, 256, GEMM_SMEM>>>(xh, xl, wh + 1*WN, wl + 1*WN, bk, 1.0f,
                                       nullptr, kh, kl, 0);
    gemm_tc<<<ggrid, 256, GEMM_SMEM>>>(xh, xl, wh + 2*WN, wl + 2*WN, bv, 1.0f,
                                       nullptr, vh, vl, 0);

    cudaFuncSetAttribute(attn_kernel, cudaFuncAttributeMaxDynamicSharedMemorySize, ATT_SMEM);
    dim3 agrid(Sq / 128, Bq * Hq);
    attn_kernel<<<agrid, 256, ATT_SMEM>>>(qh, ql, kh, kl, vh, vl, mask, ch, cl);

    gemm_tc<<<ggrid, 256, GEMM_SMEM>>>(ch, cl, wh + 3*WN, wl + 3*WN, bo, 1.0f,
                                       out, nullptr, nullptr, 1);
}